// round 1
// baseline (speedup 1.0000x reference)
#include <cuda_runtime.h>

#define BB 4096
#define TT 1024
#define NN 16
#define NP 8   // 16 filters as 8 packed f32x2 pairs

// Transposed currents scratch: [T+8][B] (8 rows of prefetch overrun padding).
// __device__ global (no runtime allocation).
__device__ float g_curT[(TT + 8) * BB];

typedef unsigned long long u64;

__device__ __forceinline__ u64 pk2(float x, float y) {
    u64 r; asm("mov.b64 %0, {%1, %2};" : "=l"(r) : "f"(x), "f"(y)); return r;
}
__device__ __forceinline__ void upk2(u64 a, float& x, float& y) {
    asm("mov.b64 {%0, %1}, %2;" : "=f"(x), "=f"(y) : "l"(a));
}
__device__ __forceinline__ u64 fma2_(u64 a, u64 b, u64 c) {
    u64 d; asm("fma.rn.f32x2 %0, %1, %2, %3;" : "=l"(d) : "l"(a), "l"(b), "l"(c)); return d;
}
__device__ __forceinline__ u64 mul2_(u64 a, u64 b) {
    u64 d; asm("mul.rn.f32x2 %0, %1, %2;" : "=l"(d) : "l"(a), "l"(b)); return d;
}
__device__ __forceinline__ u64 add2_(u64 a, u64 b) {
    u64 d; asm("add.rn.f32x2 %0, %1, %2;" : "=l"(d) : "l"(a), "l"(b)); return d;
}

// ---------------------------------------------------------------------------
// Pass 1: transpose currents (B,T) -> g_curT (T,B) so the sequential kernel's
// per-step load is one coalesced 128B line per warp.
// ---------------------------------------------------------------------------
__global__ void transpose_kernel(const float* __restrict__ cur) {
    __shared__ float tile[32][33];
    const int tx = threadIdx.x, ty = threadIdx.y;
    const int t0 = blockIdx.x * 32, b0 = blockIdx.y * 32;
#pragma unroll
    for (int i = 0; i < 32; i += 8)
        tile[ty + i][tx] = cur[(size_t)(b0 + ty + i) * TT + (t0 + tx)];
    __syncthreads();
#pragma unroll
    for (int i = 0; i < 32; i += 8)
        g_curT[(size_t)(t0 + ty + i) * BB + (b0 + tx)] = tile[tx][ty + i];
}

// ---------------------------------------------------------------------------
// Pass 2: the recurrence. One thread = one batch row. 16 filter states in
// 8 packed f32x2 registers. Per step:
//   w_n   = decay_n * v_n                     (8  FMUL2)   [reused twice]
//   S     = sum_n w_n                          (7 ADD2 + 1 FADD)
//   x     = S*cs + cur*ca + fs*cb + c0         (3 FFMA)  [algebraic refactor of
//                                               x = (mean(v_t)-g_b)/max_current]
//   poly  = Horner deg-4 in x                  (4 FFMA)
//   fs'   = MFR * max(tanh(poly), 0)           (__expf-based tanh, ~1e-6 acc)
//   v_n   = w_n + cur*a_n + fs*1000*b_n        (16 FFMA2, uses OLD fs)
// The v-update is off the fs->fs critical path (depends only on w, cur, old fs).
// ---------------------------------------------------------------------------
__global__ void __launch_bounds__(32, 1) gfr_kernel(
    const float* __restrict__ a, const float* __restrict__ b,
    const float* __restrict__ pc, const float* __restrict__ gb,
    const float* __restrict__ ds, const float* __restrict__ mc,
    const float* __restrict__ mfr, float* __restrict__ out)
{
    const int bidx = blockIdx.x * 32 + threadIdx.x;

    u64 av[NP], bv[NP], dv[NP], v[NP];
    float suma = 0.f, sumb = 0.f;
#pragma unroll
    for (int i = 0; i < NP; i++) {
        float a0 = a[2 * i],           a1 = a[2 * i + 1];
        float b0 = 1000.f * b[2 * i],  b1 = 1000.f * b[2 * i + 1];
        av[i] = pk2(a0, a1);
        bv[i] = pk2(b0, b1);
        dv[i] = pk2(1.f - ds[2 * i], 1.f - ds[2 * i + 1]);
        suma += a0 + a1;
        sumb += b0 + b1;
        v[i] = 0ull;
    }
    const float invmc = 1.f / mc[0];
    const float cs = invmc * (1.f / (float)NN);
    const float ca = suma * cs;
    const float cb = sumb * cs;
    const float c0 = -gb[0] * invmc;
    const float q0 = pc[0] * pc[0], q1 = pc[1] * pc[1], q2 = pc[2] * pc[2],
                q3 = pc[3] * pc[3], q4 = pc[4] * pc[4];
    const float MFR = mfr[0];

    const float* cp = g_curT + bidx;
    float* op = out + bidx;
    float fs = 0.f;

    constexpr int PF = 8;  // prefetch depth (steps of lookahead)
    float curbuf[PF];
#pragma unroll
    for (int i = 0; i < PF; i++) curbuf[i] = __ldg(cp + (size_t)i * BB);

    for (int t = 0; t < TT; t += PF) {
#pragma unroll
        for (int j = 0; j < PF; j++) {
            const float cur = curbuf[j];
            // prefetch PF steps ahead (padding rows make the tail loads safe)
            curbuf[j] = __ldg(cp + (size_t)(t + j + PF) * BB);

            // w = decay * v  (also first term of next v)
            u64 w[NP];
#pragma unroll
            for (int i = 0; i < NP; i++) w[i] = mul2_(dv[i], v[i]);

            // S = sum(w) via packed tree
            u64 s0 = add2_(w[0], w[1]);
            u64 s1 = add2_(w[2], w[3]);
            u64 s2 = add2_(w[4], w[5]);
            u64 s3 = add2_(w[6], w[7]);
            s0 = add2_(s0, s1);
            s2 = add2_(s2, s3);
            s0 = add2_(s0, s2);
            float sx, sy; upk2(s0, sx, sy);
            const float S = sx + sy;

            // x = (mean(v_t) - g_b) / max_current, refactored
            const float x = fmaf(S, cs, fmaf(cur, ca, fmaf(fs, cb, c0)));

            // degree-4 Horner with squared coefficients
            float p = fmaf(q4, x, q3);
            p = fmaf(p, x, q2);
            p = fmaf(p, x, q1);
            p = fmaf(p, x, q0);

            // tanh(p) = 1 - 2/(exp(2p)+1); saturates correctly at +/-inf
            const float e = __expf(p + p);
            const float th = 1.f - __fdividef(2.f, e + 1.f);
            const float fsn = MFR * fmaxf(th, 0.f);

            // v_t = w + cur*a + (old fs)*1000b   -- independent of fsn
            const u64 curp2 = pk2(cur, cur);
            const u64 fsp2  = pk2(fs, fs);
#pragma unroll
            for (int i = 0; i < NP; i++)
                v[i] = fma2_(curp2, av[i], fma2_(fsp2, bv[i], w[i]));

            op[(size_t)(t + j) * BB] = fsn;   // coalesced across the warp
            fs = fsn;
        }
    }
}

extern "C" void kernel_launch(void* const* d_in, const int* in_sizes, int n_in,
                              void* d_out, int out_size) {
    const float* currents = (const float*)d_in[0];
    const float* a   = (const float*)d_in[1];
    const float* b   = (const float*)d_in[2];
    const float* pc  = (const float*)d_in[3];
    const float* gb  = (const float*)d_in[4];
    const float* ds  = (const float*)d_in[5];
    const float* mc  = (const float*)d_in[6];
    const float* mfr = (const float*)d_in[7];
    float* out = (float*)d_out;

    dim3 tb(32, 8), tg(TT / 32, BB / 32);
    transpose_kernel<<<tg, tb>>>(currents);
    gfr_kernel<<<BB / 32, 32>>>(a, b, pc, gb, ds, mc, mfr, out);
}

// round 3
// speedup vs baseline: 1.2189x; 1.2189x over previous
#include <cuda_runtime.h>

#define BB 4096
#define TT 1024
#define NN 16
#define NPT 4   // pairs per thread: 2 threads/row * 4 pairs * 2 = 16 filters

// Transposed currents scratch: [T+8][B] (8 rows prefetch-overrun padding).
__device__ float g_curT[(TT + 8) * BB];

typedef unsigned long long u64;

__device__ __forceinline__ u64 pk2(float x, float y) {
    u64 r; asm("mov.b64 %0, {%1, %2};" : "=l"(r) : "f"(x), "f"(y)); return r;
}
__device__ __forceinline__ void upk2(u64 a, float& x, float& y) {
    asm("mov.b64 {%0, %1}, %2;" : "=f"(x), "=f"(y) : "l"(a));
}
__device__ __forceinline__ u64 fma2_(u64 a, u64 b, u64 c) {
    u64 d; asm("fma.rn.f32x2 %0, %1, %2, %3;" : "=l"(d) : "l"(a), "l"(b), "l"(c)); return d;
}
__device__ __forceinline__ u64 mul2_(u64 a, u64 b) {
    u64 d; asm("mul.rn.f32x2 %0, %1, %2;" : "=l"(d) : "l"(a), "l"(b)); return d;
}
__device__ __forceinline__ u64 add2_(u64 a, u64 b) {
    u64 d; asm("add.rn.f32x2 %0, %1, %2;" : "=l"(d) : "l"(a), "l"(b)); return d;
}
__device__ __forceinline__ float tanh_a(float x) {
    float y; asm("tanh.approx.f32 %0, %1;" : "=f"(y) : "f"(x)); return y;
}

// ---------------------------------------------------------------------------
// Pass 1: transpose currents (B,T) -> g_curT (T,B) so the sequential kernel's
// per-step load is one coalesced 128B line per warp.
// ---------------------------------------------------------------------------
__global__ void transpose_kernel(const float* __restrict__ cur) {
    __shared__ float tile[32][33];
    const int tx = threadIdx.x, ty = threadIdx.y;
    const int t0 = blockIdx.x * 32, b0 = blockIdx.y * 32;
#pragma unroll
    for (int i = 0; i < 32; i += 8)
        tile[ty + i][tx] = cur[(size_t)(b0 + ty + i) * TT + (t0 + tx)];
    __syncthreads();
#pragma unroll
    for (int i = 0; i < 32; i += 8)
        g_curT[(size_t)(t0 + ty + i) * BB + (b0 + tx)] = tile[tx][ty + i];
}

// ---------------------------------------------------------------------------
// Pass 2: recurrence. TWO threads per batch row; each owns 8 filters
// (4 packed f32x2 pairs). Carried nonlinearity variable is th (fs = MFR*th,
// MFR folded into the b coefficients and the output scale).
//
// relu/tanh refactor (exact): relu(MFR*tanh(p)) == MFR*tanh(max(p,0)) for
// MFR>0, since tanh is odd/monotone. So the chain nonlinearity is one
// MUFU.TANH after an FMNMX.
//
// Per step (~36 instrs, chain ~36 cyc):
//   w    = decay*v                       (4 MUL2)    [reused for v update]
//   Wp   = packed tree sum of w          (3 ADD2 + unpack + FADD)
//   W    = Wp + shfl_xor(Wp,1)           (SHFL hides in 2-step W-path slack)
//   base = fma(W, csN, pre_j)            (pre_j = fma(cur,ca,c0), precomputed)
//   x    = fma(th, cb, base)             <- critical path resumes here
//   p    = Estrin deg-4 in x             (depth 12)
//   th'  = tanh.approx(max(p,0))         (FMNMX + MUFU.TANH)
//   v    = w + cur*a + th*bM             (8 FMA2, uses OLD th)
// ---------------------------------------------------------------------------
__global__ void __launch_bounds__(32) gfr_kernel(
    const float* __restrict__ a, const float* __restrict__ b,
    const float* __restrict__ pc, const float* __restrict__ gb,
    const float* __restrict__ ds, const float* __restrict__ mc,
    const float* __restrict__ mfr, float* __restrict__ out)
{
    const int lane = threadIdx.x;
    const int sub  = lane & 1;                       // which half of the filters
    const int row  = blockIdx.x * 16 + (lane >> 1);  // batch row
    const int f0   = sub * 8;                        // first filter index

    const float MFR = mfr[0];
    const float invmc = 1.f / mc[0];
    const float csN = invmc * (1.f / (float)NN);

    u64 av[NPT], bv[NPT], dv[NPT], v[NPT];
#pragma unroll
    for (int i = 0; i < NPT; i++) {
        av[i] = pk2(a[f0 + 2 * i], a[f0 + 2 * i + 1]);
        bv[i] = pk2(1000.f * MFR * b[f0 + 2 * i], 1000.f * MFR * b[f0 + 2 * i + 1]);
        dv[i] = pk2(1.f - ds[f0 + 2 * i], 1.f - ds[f0 + 2 * i + 1]);
        v[i] = 0ull;
    }
    // full-sum constants (over ALL 16 filters)
    float suma = 0.f, sumb = 0.f;
#pragma unroll
    for (int n = 0; n < NN; n++) { suma += a[n]; sumb += b[n]; }
    const float ca = suma * csN;                 // currents feed-through term
    const float cb = 1000.f * MFR * sumb * csN;  // th feedback term
    const float c0 = -gb[0] * invmc;
    const float q0 = pc[0] * pc[0], q1 = pc[1] * pc[1], q2 = pc[2] * pc[2],
                q3 = pc[3] * pc[3], q4 = pc[4] * pc[4];

    const float* cp = g_curT + row;
    float* op = out + row;
    float th = 0.f;

    constexpr int PF = 8;
    float curbuf[PF], prebuf[PF];
#pragma unroll
    for (int i = 0; i < PF; i++) {
        curbuf[i] = __ldg(cp + (size_t)i * BB);
        prebuf[i] = fmaf(curbuf[i], ca, c0);
    }

    for (int t = 0; t < TT; t += PF) {
#pragma unroll
        for (int j = 0; j < PF; j++) {
            const float cur = curbuf[j];
            const float pre = prebuf[j];
            // prefetch PF ahead (padding rows cover the tail)
            curbuf[j] = __ldg(cp + (size_t)(t + j + PF) * BB);
            prebuf[j] = fmaf(curbuf[j], ca, c0);

            // w = decay * v
            u64 w[NPT];
#pragma unroll
            for (int i = 0; i < NPT; i++) w[i] = mul2_(dv[i], v[i]);

            // partial sum of this thread's 8 filters
            u64 s0 = add2_(w[0], w[1]);
            u64 s1 = add2_(w[2], w[3]);
            s0 = add2_(s0, s1);
            float sx, sy; upk2(s0, sx, sy);
            float Wp = sx + sy;
            // combine with partner thread (other 8 filters)
            const float W = Wp + __shfl_xor_sync(0xFFFFFFFFu, Wp, 1);

            const float base = fmaf(W, csN, pre);
            // ---- critical path: from old th ----
            const float x = fmaf(th, cb, base);
            const float x2 = x * x;
            const float u01 = fmaf(q1, x, q0);
            const float u34 = fmaf(q4, x, q3);
            const float w1s = fmaf(q2, x2, u01);
            const float x3 = x * x2;
            float p = fmaf(u34, x3, w1s);
            p = fmaxf(p, 0.f);
            const float thn = tanh_a(p);
            // ------------------------------------

            // v_t = w + cur*a + (OLD th)*bM
            const u64 curp2 = pk2(cur, cur);
            const u64 thp2  = pk2(th, th);
#pragma unroll
            for (int i = 0; i < NPT; i++)
                v[i] = fma2_(curp2, av[i], fma2_(thp2, bv[i], w[i]));

            if (sub == 0) op[(size_t)(t + j) * BB] = MFR * thn;
            th = thn;
        }
    }
}

extern "C" void kernel_launch(void* const* d_in, const int* in_sizes, int n_in,
                              void* d_out, int out_size) {
    const float* currents = (const float*)d_in[0];
    const float* a   = (const float*)d_in[1];
    const float* b   = (const float*)d_in[2];
    const float* pc  = (const float*)d_in[3];
    const float* gb  = (const float*)d_in[4];
    const float* ds  = (const float*)d_in[5];
    const float* mc  = (const float*)d_in[6];
    const float* mfr = (const float*)d_in[7];
    float* out = (float*)d_out;

    dim3 tb(32, 8), tg(TT / 32, BB / 32);
    transpose_kernel<<<tg, tb>>>(currents);
    // 2 threads per row: 8192 threads, 256 blocks of 32
    gfr_kernel<<<(2 * BB) / 32, 32>>>(a, b, pc, gb, ds, mc, mfr, out);
}

// round 4
// speedup vs baseline: 1.3828x; 1.1345x over previous
#include <cuda_runtime.h>

#define BB 4096
#define TT 1024
#define NN 16
#define NPT 2   // packed pairs per thread: 4 threads/row * 2 pairs * 2 = 16 filters

// Transposed currents scratch: [T+8][B] (8 rows prefetch-overrun padding).
__device__ float g_curT[(TT + 8) * BB];

typedef unsigned long long u64;

__device__ __forceinline__ u64 pk2(float x, float y) {
    u64 r; asm("mov.b64 %0, {%1, %2};" : "=l"(r) : "f"(x), "f"(y)); return r;
}
__device__ __forceinline__ void upk2(u64 a, float& x, float& y) {
    asm("mov.b64 {%0, %1}, %2;" : "=f"(x), "=f"(y) : "l"(a));
}
__device__ __forceinline__ u64 fma2_(u64 a, u64 b, u64 c) {
    u64 d; asm("fma.rn.f32x2 %0, %1, %2, %3;" : "=l"(d) : "l"(a), "l"(b), "l"(c)); return d;
}
__device__ __forceinline__ u64 mul2_(u64 a, u64 b) {
    u64 d; asm("mul.rn.f32x2 %0, %1, %2;" : "=l"(d) : "l"(a), "l"(b)); return d;
}
__device__ __forceinline__ u64 add2_(u64 a, u64 b) {
    u64 d; asm("add.rn.f32x2 %0, %1, %2;" : "=l"(d) : "l"(a), "l"(b)); return d;
}
__device__ __forceinline__ float tanh_a(float x) {
    float y; asm("tanh.approx.f32 %0, %1;" : "=f"(y) : "f"(x)); return y;
}

// ---------------------------------------------------------------------------
// Pass 1: transpose currents (B,T) -> g_curT (T,B).
// ---------------------------------------------------------------------------
__global__ void transpose_kernel(const float* __restrict__ cur) {
    __shared__ float tile[32][33];
    const int tx = threadIdx.x, ty = threadIdx.y;
    const int t0 = blockIdx.x * 32, b0 = blockIdx.y * 32;
#pragma unroll
    for (int i = 0; i < 32; i += 8)
        tile[ty + i][tx] = cur[(size_t)(b0 + ty + i) * TT + (t0 + tx)];
    __syncthreads();
#pragma unroll
    for (int i = 0; i < 32; i += 8)
        g_curT[(size_t)(t0 + ty + i) * BB + (b0 + tx)] = tile[tx][ty + i];
}

// ---------------------------------------------------------------------------
// Pass 2: recurrence. FOUR threads per batch row; each owns 4 filters
// (2 packed f32x2 pairs). Blocks of 128 threads / grid 128: one block per SM,
// one warp per SMSP (this was the R3 bug: 32-thread blocks stacked every
// warp on SMSP0).
//
// The 4-lane W reduction uses THREE PARALLEL shfl_xor (1,2,3) so only one
// 26-cyc SHFL latency sits in the 2-step W loop.
//
// Carried variable th (fs = MFR*th; MFR folded into b coeffs + output).
// relu∘(MFR·tanh) == MFR·tanh∘relu (exact, MFR>0).
// ---------------------------------------------------------------------------
__global__ void __launch_bounds__(128, 1) gfr_kernel(
    const float* __restrict__ a, const float* __restrict__ b,
    const float* __restrict__ pc, const float* __restrict__ gb,
    const float* __restrict__ ds, const float* __restrict__ mc,
    const float* __restrict__ mfr, float* __restrict__ out)
{
    const int tid = threadIdx.x;
    const int sub = tid & 3;                         // lane within the row-group
    const int row = blockIdx.x * 32 + (tid >> 2);    // batch row
    const int f0  = sub * 4;                         // first filter index

    const float MFR = mfr[0];
    const float invmc = 1.f / mc[0];
    const float csN = invmc * (1.f / (float)NN);

    u64 av[NPT], bv[NPT], dv[NPT], v[NPT];
#pragma unroll
    for (int i = 0; i < NPT; i++) {
        av[i] = pk2(a[f0 + 2 * i], a[f0 + 2 * i + 1]);
        bv[i] = pk2(1000.f * MFR * b[f0 + 2 * i], 1000.f * MFR * b[f0 + 2 * i + 1]);
        dv[i] = pk2(1.f - ds[f0 + 2 * i], 1.f - ds[f0 + 2 * i + 1]);
        v[i] = 0ull;
    }
    // full-sum constants over ALL 16 filters
    float suma = 0.f, sumb = 0.f;
#pragma unroll
    for (int n = 0; n < NN; n++) { suma += a[n]; sumb += b[n]; }
    const float ca = suma * csN;                 // currents feed-through
    const float cb = 1000.f * MFR * sumb * csN;  // th feedback
    const float c0 = -gb[0] * invmc;
    const float q0 = pc[0] * pc[0], q1 = pc[1] * pc[1], q2 = pc[2] * pc[2],
                q3 = pc[3] * pc[3], q4 = pc[4] * pc[4];

    const float* cp = g_curT + row;
    float* op = out + row;
    float th = 0.f;

    constexpr int PF = 8;
    float curbuf[PF], prebuf[PF];
#pragma unroll
    for (int i = 0; i < PF; i++) {
        curbuf[i] = __ldg(cp + (size_t)i * BB);
        prebuf[i] = fmaf(curbuf[i], ca, c0);
    }

    for (int t = 0; t < TT; t += PF) {
#pragma unroll
        for (int j = 0; j < PF; j++) {
            const float cur = curbuf[j];
            const float pre = prebuf[j];
            curbuf[j] = __ldg(cp + (size_t)(t + j + PF) * BB);
            prebuf[j] = fmaf(curbuf[j], ca, c0);

            // w = decay * v  (reused for v update)
            u64 w0 = mul2_(dv[0], v[0]);
            u64 w1 = mul2_(dv[1], v[1]);

            // own partial sum (4 filters)
            u64 s = add2_(w0, w1);
            float sx, sy; upk2(s, sx, sy);
            const float Wp = sx + sy;

            // 3 parallel shuffles: all partner partials at once
            const float A = __shfl_xor_sync(0xFFFFFFFFu, Wp, 1);
            const float Bx = __shfl_xor_sync(0xFFFFFFFFu, Wp, 2);
            const float C = __shfl_xor_sync(0xFFFFFFFFu, Wp, 3);
            const float W = (Wp + A) + (Bx + C);

            const float base = fmaf(W, csN, pre);
            // ---- th critical path ----
            const float x = fmaf(th, cb, base);
            const float x2 = x * x;
            const float u01 = fmaf(q1, x, q0);
            const float u34 = fmaf(q4, x, q3);
            const float w1s = fmaf(q2, x2, u01);
            const float x3 = x * x2;
            float p = fmaf(u34, x3, w1s);
            p = fmaxf(p, 0.f);
            const float thn = tanh_a(p);
            // --------------------------

            // v_t = w + cur*a + (OLD th)*bM
            const u64 curp2 = pk2(cur, cur);
            const u64 thp2  = pk2(th, th);
            v[0] = fma2_(curp2, av[0], fma2_(thp2, bv[0], w0));
            v[1] = fma2_(curp2, av[1], fma2_(thp2, bv[1], w1));

            if (sub == 0) op[(size_t)(t + j) * BB] = MFR * thn;
            th = thn;
        }
    }
}

extern "C" void kernel_launch(void* const* d_in, const int* in_sizes, int n_in,
                              void* d_out, int out_size) {
    const float* currents = (const float*)d_in[0];
    const float* a   = (const float*)d_in[1];
    const float* b   = (const float*)d_in[2];
    const float* pc  = (const float*)d_in[3];
    const float* gb  = (const float*)d_in[4];
    const float* ds  = (const float*)d_in[5];
    const float* mc  = (const float*)d_in[6];
    const float* mfr = (const float*)d_in[7];
    float* out = (float*)d_out;

    dim3 tb(32, 8), tg(TT / 32, BB / 32);
    transpose_kernel<<<tg, tb>>>(currents);
    // 4 threads/row: 16384 threads = 128 blocks x 128 -> 1 block/SM, 1 warp/SMSP
    gfr_kernel<<<(4 * BB) / 128, 128>>>(a, b, pc, gb, ds, mc, mfr, out);
}

// round 5
// speedup vs baseline: 1.3846x; 1.0013x over previous
#include <cuda_runtime.h>

#define BB 4096
#define TT 1024
#define NN 16
#define NPT 2   // packed pairs per thread: 4 threads/row * 2 pairs * 2 = 16 filters

// Transposed currents scratch: [T+8][B] (8 rows prefetch-overrun padding).
__device__ float g_curT[(TT + 8) * BB];

typedef unsigned long long u64;

__device__ __forceinline__ u64 pk2(float x, float y) {
    u64 r; asm("mov.b64 %0, {%1, %2};" : "=l"(r) : "f"(x), "f"(y)); return r;
}
__device__ __forceinline__ void upk2(u64 a, float& x, float& y) {
    asm("mov.b64 {%0, %1}, %2;" : "=f"(x), "=f"(y) : "l"(a));
}
__device__ __forceinline__ u64 fma2_(u64 a, u64 b, u64 c) {
    u64 d; asm("fma.rn.f32x2 %0, %1, %2, %3;" : "=l"(d) : "l"(a), "l"(b), "l"(c)); return d;
}
__device__ __forceinline__ u64 mul2_(u64 a, u64 b) {
    u64 d; asm("mul.rn.f32x2 %0, %1, %2;" : "=l"(d) : "l"(a), "l"(b)); return d;
}
__device__ __forceinline__ u64 add2_(u64 a, u64 b) {
    u64 d; asm("add.rn.f32x2 %0, %1, %2;" : "=l"(d) : "l"(a), "l"(b)); return d;
}
__device__ __forceinline__ float tanh_a(float x) {
    float y; asm("tanh.approx.f32 %0, %1;" : "=f"(y) : "f"(x)); return y;
}

// ---------------------------------------------------------------------------
// Pass 1: transpose currents (B,T) -> g_curT (T,B).
// ---------------------------------------------------------------------------
__global__ void transpose_kernel(const float* __restrict__ cur) {
    __shared__ float tile[32][33];
    const int tx = threadIdx.x, ty = threadIdx.y;
    const int t0 = blockIdx.x * 32, b0 = blockIdx.y * 32;
#pragma unroll
    for (int i = 0; i < 32; i += 8)
        tile[ty + i][tx] = cur[(size_t)(b0 + ty + i) * TT + (t0 + tx)];
    __syncthreads();
#pragma unroll
    for (int i = 0; i < 32; i += 8)
        g_curT[(size_t)(t0 + ty + i) * BB + (b0 + tx)] = tile[tx][ty + i];
}

// ---------------------------------------------------------------------------
// Pass 2: recurrence. FOUR threads per batch row; each owns 4 filters
// (2 packed f32x2 pairs). 128 blocks x 128 threads: 1 block/SM, 1 warp/SMSP.
//
// KEY FIX vs R4: the prefetched LDG result is NEVER consumed in the same
// iteration it was issued. curbuf[j] ages PF=8 steps (~400+ cyc of slack)
// before `pre = fma(cur, ca, c0)` touches it, so no L2-hit latency (~260cyc)
// is exposed on the critical loop.
//
// Carried variable th (fs = MFR*th; MFR folded into b coeffs + output).
// relu∘(MFR·tanh) == MFR·tanh∘relu (exact, MFR>0).
// ---------------------------------------------------------------------------
__global__ void __launch_bounds__(128, 1) gfr_kernel(
    const float* __restrict__ a, const float* __restrict__ b,
    const float* __restrict__ pc, const float* __restrict__ gb,
    const float* __restrict__ ds, const float* __restrict__ mc,
    const float* __restrict__ mfr, float* __restrict__ out)
{
    const int tid = threadIdx.x;
    const int sub = tid & 3;                         // lane within row-group
    const int row = blockIdx.x * 32 + (tid >> 2);    // batch row
    const int f0  = sub * 4;                         // first filter index

    const float MFR = mfr[0];
    const float invmc = 1.f / mc[0];
    const float csN = invmc * (1.f / (float)NN);

    u64 av[NPT], bv[NPT], dv[NPT], v[NPT];
#pragma unroll
    for (int i = 0; i < NPT; i++) {
        av[i] = pk2(a[f0 + 2 * i], a[f0 + 2 * i + 1]);
        bv[i] = pk2(1000.f * MFR * b[f0 + 2 * i], 1000.f * MFR * b[f0 + 2 * i + 1]);
        dv[i] = pk2(1.f - ds[f0 + 2 * i], 1.f - ds[f0 + 2 * i + 1]);
        v[i] = 0ull;
    }
    // full-sum constants over ALL 16 filters
    float suma = 0.f, sumb = 0.f;
#pragma unroll
    for (int n = 0; n < NN; n++) { suma += a[n]; sumb += b[n]; }
    const float ca = suma * csN;                 // currents feed-through
    const float cb = 1000.f * MFR * sumb * csN;  // th feedback
    const float c0 = -gb[0] * invmc;
    const float q0 = pc[0] * pc[0], q1 = pc[1] * pc[1], q2 = pc[2] * pc[2],
                q3 = pc[3] * pc[3], q4 = pc[4] * pc[4];

    const float* cp = g_curT + row;
    float* op = out + row;
    float th = 0.f;

    constexpr int PF = 8;
    float curbuf[PF];
#pragma unroll
    for (int i = 0; i < PF; i++) curbuf[i] = __ldg(cp + (size_t)i * BB);

    for (int t = 0; t < TT; t += PF) {
#pragma unroll
        for (int j = 0; j < PF; j++) {
            const float cur = curbuf[j];                         // PF-steps old
            curbuf[j] = __ldg(cp + (size_t)(t + j + PF) * BB);   // not consumed here
            const float pre = fmaf(cur, ca, c0);                 // off critical path

            // w = decay * v  (reused for v update)
            u64 w0 = mul2_(dv[0], v[0]);
            u64 w1 = mul2_(dv[1], v[1]);

            // own partial sum (4 filters)
            u64 s = add2_(w0, w1);
            float sx, sy; upk2(s, sx, sy);
            const float Wp = sx + sy;

            // 3 parallel shuffles: all partner partials at once
            const float A  = __shfl_xor_sync(0xFFFFFFFFu, Wp, 1);
            const float Bx = __shfl_xor_sync(0xFFFFFFFFu, Wp, 2);
            const float C  = __shfl_xor_sync(0xFFFFFFFFu, Wp, 3);
            const float W = (Wp + A) + (Bx + C);

            const float base = fmaf(W, csN, pre);
            // ---- th critical path ----
            const float x = fmaf(th, cb, base);
            const float x2 = x * x;
            const float u01 = fmaf(q1, x, q0);
            const float u34 = fmaf(q4, x, q3);
            const float w1s = fmaf(q2, x2, u01);
            const float x3 = x * x2;
            float p = fmaf(u34, x3, w1s);
            p = fmaxf(p, 0.f);
            const float thn = tanh_a(p);
            // --------------------------

            // v_t = w + cur*a + (OLD th)*bM
            const u64 curp2 = pk2(cur, cur);
            const u64 thp2  = pk2(th, th);
            v[0] = fma2_(curp2, av[0], fma2_(thp2, bv[0], w0));
            v[1] = fma2_(curp2, av[1], fma2_(thp2, bv[1], w1));

            if (sub == 0) op[(size_t)(t + j) * BB] = MFR * thn;
            th = thn;
        }
    }
}

extern "C" void kernel_launch(void* const* d_in, const int* in_sizes, int n_in,
                              void* d_out, int out_size) {
    const float* currents = (const float*)d_in[0];
    const float* a   = (const float*)d_in[1];
    const float* b   = (const float*)d_in[2];
    const float* pc  = (const float*)d_in[3];
    const float* gb  = (const float*)d_in[4];
    const float* ds  = (const float*)d_in[5];
    const float* mc  = (const float*)d_in[6];
    const float* mfr = (const float*)d_in[7];
    float* out = (float*)d_out;

    dim3 tb(32, 8), tg(TT / 32, BB / 32);
    transpose_kernel<<<tg, tb>>>(currents);
    // 4 threads/row: 16384 threads = 128 blocks x 128 -> 1 block/SM, 1 warp/SMSP
    gfr_kernel<<<(4 * BB) / 128, 128>>>(a, b, pc, gb, ds, mc, mfr, out);
}